// round 16
// baseline (speedup 1.0000x reference)
#include <cuda_runtime.h>
#include <cuda_fp16.h>
#include <math.h>
#include <stdint.h>

#define NTOK 8192      // B * L = 4 * 2048
#define DMODEL 512
#define HDIM 64
#define FDIM 2048
#define NEXP 4
#define SEQ 2048

// ---------------- scratch (device globals; no allocation allowed) ----------
__device__ __half g_qkv[(size_t)NTOK * 1024];  // q/k projections (fp16)
__device__ __half g_vt[(size_t)NTOK * 512];    // V^T fp16: [b*512+d][token]
__device__ float g_attn[(size_t)NTOK * DMODEL];
__device__ float g_tmp[(size_t)NTOK * DMODEL];
__device__ float g_x1[(size_t)NTOK * DMODEL];
__device__ float g_x2[(size_t)NTOK * DMODEL];
__device__ float g_h[(size_t)NTOK * FDIM];
__device__ float g_w1t[(size_t)NEXP * DMODEL * FDIM];  // [E][2048][512]
__device__ float g_w2t[(size_t)NEXP * FDIM * DMODEL];  // [E][512][2048]
__device__ int   g_cnt[NEXP];
__device__ int   g_list[NEXP * NTOK];

#define QSCALE_C 0.18033688011112042f   // 0.125 * log2(e)

__global__ void zero_cnt_kernel() {
    if (threadIdx.x < NEXP) g_cnt[threadIdx.x] = 0;
}

// ---------------- tiled transpose: in[z][R][C] -> out[z][C][R] --------------
__global__ void __launch_bounds__(256) transpose_k(
    const float* __restrict__ in, float* __restrict__ out, int R, int C)
{
    __shared__ float tile[32][33];
    const int bx = blockIdx.x * 32, by = blockIdx.y * 32;
    const float* src = in + (size_t)blockIdx.z * R * C;
    float* dst = out + (size_t)blockIdx.z * R * C;
#pragma unroll
    for (int i = 0; i < 32; i += 8)
        tile[threadIdx.y + i][threadIdx.x] =
            src[(size_t)(by + threadIdx.y + i) * C + bx + threadIdx.x];
    __syncthreads();
#pragma unroll
    for (int i = 0; i < 32; i += 8)
        dst[(size_t)(bx + threadIdx.y + i) * R + by + threadIdx.x] =
            tile[threadIdx.x][threadIdx.y + i];
}

// ---------------- mma / ldmatrix / cp.async helpers -------------------------
__device__ __forceinline__ void mma8(float* c, uint32_t a0, uint32_t a1,
                                     uint32_t a2, uint32_t a3,
                                     uint32_t b0, uint32_t b1) {
    asm volatile(
        "mma.sync.aligned.m16n8k8.row.col.f32.tf32.tf32.f32 "
        "{%0,%1,%2,%3},{%4,%5,%6,%7},{%8,%9},{%0,%1,%2,%3};"
        : "+f"(c[0]), "+f"(c[1]), "+f"(c[2]), "+f"(c[3])
        : "r"(a0), "r"(a1), "r"(a2), "r"(a3), "r"(b0), "r"(b1));
}

__device__ __forceinline__ void mma16h(float* c, uint32_t a0, uint32_t a1,
                                       uint32_t a2, uint32_t a3,
                                       uint32_t b0, uint32_t b1) {
    asm volatile(
        "mma.sync.aligned.m16n8k16.row.col.f32.f16.f16.f32 "
        "{%0,%1,%2,%3},{%4,%5,%6,%7},{%8,%9},{%0,%1,%2,%3};"
        : "+f"(c[0]), "+f"(c[1]), "+f"(c[2]), "+f"(c[3])
        : "r"(a0), "r"(a1), "r"(a2), "r"(a3), "r"(b0), "r"(b1));
}

__device__ __forceinline__ void ldsm4(uint32_t& r0, uint32_t& r1,
                                      uint32_t& r2, uint32_t& r3, uint32_t addr) {
    asm volatile("ldmatrix.sync.aligned.m8n8.x4.shared.b16 {%0,%1,%2,%3}, [%4];"
                 : "=r"(r0), "=r"(r1), "=r"(r2), "=r"(r3) : "r"(addr));
}

__device__ __forceinline__ uint32_t smem_u32(const void* p) {
    return (uint32_t)__cvta_generic_to_shared(p);
}

__device__ __forceinline__ void cp16(uint32_t s, const void* g) {
    asm volatile("cp.async.cg.shared.global [%0], [%1], 16;"
                 :: "r"(s), "l"(g));
}
__device__ __forceinline__ void cp16p(uint32_t s, const void* g, bool pred) {
    int sz = pred ? 16 : 0;
    asm volatile("cp.async.cg.shared.global [%0], [%1], 16, %2;"
                 :: "r"(s), "l"(g), "r"(sz));
}
#define CP_COMMIT() asm volatile("cp.async.commit_group;" ::: "memory")
#define CP_WAIT0()  asm volatile("cp.async.wait_group 0;" ::: "memory")
#define CP_WAIT1()  asm volatile("cp.async.wait_group 1;" ::: "memory")

__device__ __forceinline__ uint32_t a_lane_off(int lane, int S) {
    return (uint32_t)(((lane & 15) * S + ((lane >> 4) << 2)) << 2);
}
__device__ __forceinline__ uint32_t b_lane_off(int lane, int S) {
    return (uint32_t)((((lane & 7) + ((lane >> 4) << 3)) * S +
                       (((lane >> 3) & 1) << 2)) << 2);
}

__device__ __forceinline__ float ex2(float x) {
    float y;
    asm("ex2.approx.f32 %0, %1;" : "=f"(y) : "f"(x));
    return y;
}

__device__ __forceinline__ uint32_t pack_f16(float lo, float hi) {
    uint32_t r;
    asm("cvt.rn.f16x2.f32 %0, %1, %2;" : "=r"(r) : "f"(hi), "f"(lo));
    return r;
}

// ---------------- GEMM mainloop constants -----------------------------------
#define G_ASTG (128 * 36)
#define G_BSTG (64 * 36)
#define GEMM_SMEM ((G_ASTG + G_BSTG) * 2 * 4)

// ---------------- GEMM: C[M,N] = A[M,K] @ B[N,K]^T + bias (+resid), fp32 out
__global__ void __launch_bounds__(256) gemm_nt(
    const float* __restrict__ A, const float* __restrict__ Bw,
    const float* __restrict__ bias, const float* __restrict__ resid,
    float* __restrict__ C, int M, int N, int K)
{
    extern __shared__ uint32_t dsm[];
    uint32_t* As = dsm;
    uint32_t* Bs = dsm + 2 * G_ASTG;
    const int t = threadIdx.x;
    const int lane = t & 31, wid = t >> 5;
    const int gid = lane >> 2, tig = lane & 3;
    const int wm = (wid & 3) * 32, wn = (wid >> 2) * 32;
    const int row0 = blockIdx.y * 128, col0 = blockIdx.x * 64;
    const int lr = t >> 3, lc = (t & 7) * 4;

    const uint32_t as_st = smem_u32(As) + (uint32_t)((lr * 36 + lc) << 2);
    const uint32_t bs_st = smem_u32(Bs) + (uint32_t)((lr * 36 + lc) << 2);
    const uint32_t a_ld0 = smem_u32(As) + (uint32_t)((wm * 36) << 2) + a_lane_off(lane, 36);
    const uint32_t b_ld0 = smem_u32(Bs) + (uint32_t)((wn * 36) << 2) + b_lane_off(lane, 36);
    const uint32_t A_HALF = 16 * 36 * 4;

    const int nIter = K >> 5;
#pragma unroll
    for (int p = 0; p < 4; ++p)
        cp16(as_st + (uint32_t)(p * 32 * 36 * 4), &A[(size_t)(row0 + lr + p * 32) * K + lc]);
#pragma unroll
    for (int p = 0; p < 2; ++p)
        cp16(bs_st + (uint32_t)(p * 32 * 36 * 4), &Bw[(size_t)(col0 + lr + p * 32) * K + lc]);
    CP_COMMIT();

    float acc[2][4][4] = {};
    for (int it = 0; it < nIter; ++it) {
        const int cur = it & 1;
        const bool more = (it + 1) < nIter;
        if (more) {
            const int k0 = (it + 1) << 5;
            const uint32_t so = (uint32_t)(((cur ^ 1) ? G_ASTG : 0) << 2);
            const uint32_t sb = (uint32_t)(((cur ^ 1) ? G_BSTG : 0) << 2);
#pragma unroll
            for (int p = 0; p < 4; ++p)
                cp16(as_st + so + (uint32_t)(p * 32 * 36 * 4),
                     &A[(size_t)(row0 + lr + p * 32) * K + k0 + lc]);
#pragma unroll
            for (int p = 0; p < 2; ++p)
                cp16(bs_st + sb + (uint32_t)(p * 32 * 36 * 4),
                     &Bw[(size_t)(col0 + lr + p * 32) * K + k0 + lc]);
            CP_COMMIT();
            CP_WAIT1();
        } else {
            CP_WAIT0();
        }
        __syncthreads();
        const uint32_t a_ld = a_ld0 + (uint32_t)((cur ? G_ASTG : 0) << 2);
        const uint32_t b_ld = b_ld0 + (uint32_t)((cur ? G_BSTG : 0) << 2);
#pragma unroll
        for (int s = 0; s < 4; ++s) {
            uint32_t a0[4], a1[4], b0[4], b1[4];
            ldsm4(a0[0], a0[1], a0[2], a0[3], a_ld + s * 32);
            ldsm4(a1[0], a1[1], a1[2], a1[3], a_ld + s * 32 + A_HALF);
            ldsm4(b0[0], b0[1], b0[2], b0[3], b_ld + s * 32);
            ldsm4(b1[0], b1[1], b1[2], b1[3], b_ld + s * 32 + A_HALF);
            mma8(acc[0][0], a0[0], a0[1], a0[2], a0[3], b0[0], b0[1]);
            mma8(acc[0][1], a0[0], a0[1], a0[2], a0[3], b0[2], b0[3]);
            mma8(acc[0][2], a0[0], a0[1], a0[2], a0[3], b1[0], b1[1]);
            mma8(acc[0][3], a0[0], a0[1], a0[2], a0[3], b1[2], b1[3]);
            mma8(acc[1][0], a1[0], a1[1], a1[2], a1[3], b0[0], b0[1]);
            mma8(acc[1][1], a1[0], a1[1], a1[2], a1[3], b0[2], b0[3]);
            mma8(acc[1][2], a1[0], a1[1], a1[2], a1[3], b1[0], b1[1]);
            mma8(acc[1][3], a1[0], a1[1], a1[2], a1[3], b1[2], b1[3]);
        }
        if (more) __syncthreads();
    }

#pragma unroll
    for (int j = 0; j < 4; ++j) {
        const int c = col0 + wn + j * 8 + 2 * tig;
        float2 bj = *(const float2*)&bias[c];
#pragma unroll
        for (int i = 0; i < 2; ++i) {
            const int r0 = row0 + wm + i * 16 + gid;
            float2 v0 = make_float2(acc[i][j][0] + bj.x, acc[i][j][1] + bj.y);
            float2 v1 = make_float2(acc[i][j][2] + bj.x, acc[i][j][3] + bj.y);
            if (resid) {
                float2 q0 = *(const float2*)&resid[(size_t)r0 * N + c];
                float2 q1 = *(const float2*)&resid[(size_t)(r0 + 8) * N + c];
                v0.x += q0.x; v0.y += q0.y; v1.x += q1.x; v1.y += q1.y;
            }
            *(float2*)&C[(size_t)r0 * N + c] = v0;
            *(float2*)&C[(size_t)(r0 + 8) * N + c] = v1;
        }
    }
}

// ---------------- fused projection GEMM, all-fp16 outputs -------------------
// cols < split  -> C1 fp16 row-major (leading dim ldc1); cols < qscale_end
//                  are additionally scaled by QSCALE_C (the q columns)
// cols >= split -> Ct fp16 transposed: Ct[(b*512 + (c-split)) * SEQ + l]
__global__ void __launch_bounds__(256) gemm_proj(
    const float* __restrict__ A, const float* __restrict__ Bw,
    const float* __restrict__ bias, __half* __restrict__ C1, int ldc1,
    __half* __restrict__ Ct, int M, int N, int K, int split,
    int qscale_end)
{
    extern __shared__ uint32_t dsm[];
    uint32_t* As = dsm;
    uint32_t* Bs = dsm + 2 * G_ASTG;
    const int t = threadIdx.x;
    const int lane = t & 31, wid = t >> 5;
    const int gid = lane >> 2, tig = lane & 3;
    const int wm = (wid & 3) * 32, wn = (wid >> 2) * 32;
    const int row0 = blockIdx.y * 128, col0 = blockIdx.x * 64;
    const int lr = t >> 3, lc = (t & 7) * 4;

    const uint32_t as_st = smem_u32(As) + (uint32_t)((lr * 36 + lc) << 2);
    const uint32_t bs_st = smem_u32(Bs) + (uint32_t)((lr * 36 + lc) << 2);
    const uint32_t a_ld0 = smem_u32(As) + (uint32_t)((wm * 36) << 2) + a_lane_off(lane, 36);
    const uint32_t b_ld0 = smem_u32(Bs) + (uint32_t)((wn * 36) << 2) + b_lane_off(lane, 36);
    const uint32_t A_HALF = 16 * 36 * 4;

    const int nIter = K >> 5;
#pragma unroll
    for (int p = 0; p < 4; ++p)
        cp16(as_st + (uint32_t)(p * 32 * 36 * 4), &A[(size_t)(row0 + lr + p * 32) * K + lc]);
#pragma unroll
    for (int p = 0; p < 2; ++p)
        cp16(bs_st + (uint32_t)(p * 32 * 36 * 4), &Bw[(size_t)(col0 + lr + p * 32) * K + lc]);
    CP_COMMIT();

    float acc[2][4][4] = {};
    for (int it = 0; it < nIter; ++it) {
        const int cur = it & 1;
        const bool more = (it + 1) < nIter;
        if (more) {
            const int k0 = (it + 1) << 5;
            const uint32_t so = (uint32_t)(((cur ^ 1) ? G_ASTG : 0) << 2);
            const uint32_t sb = (uint32_t)(((cur ^ 1) ? G_BSTG : 0) << 2);
#pragma unroll
            for (int p = 0; p < 4; ++p)
                cp16(as_st + so + (uint32_t)(p * 32 * 36 * 4),
                     &A[(size_t)(row0 + lr + p * 32) * K + k0 + lc]);
#pragma unroll
            for (int p = 0; p < 2; ++p)
                cp16(bs_st + sb + (uint32_t)(p * 32 * 36 * 4),
                     &Bw[(size_t)(col0 + lr + p * 32) * K + k0 + lc]);
            CP_COMMIT();
            CP_WAIT1();
        } else {
            CP_WAIT0();
        }
        __syncthreads();
        const uint32_t a_ld = a_ld0 + (uint32_t)((cur ? G_ASTG : 0) << 2);
        const uint32_t b_ld = b_ld0 + (uint32_t)((cur ? G_BSTG : 0) << 2);
#pragma unroll
        for (int s = 0; s < 4; ++s) {
            uint32_t a0[4], a1[4], b0[4], b1[4];
            ldsm4(a0[0], a0[1], a0[2], a0[3], a_ld + s * 32);
            ldsm4(a1[0], a1[1], a1[2], a1[3], a_ld + s * 32 + A_HALF);
            ldsm4(b0[0], b0[1], b0[2], b0[3], b_ld + s * 32);
            ldsm4(b1[0], b1[1], b1[2], b1[3], b_ld + s * 32 + A_HALF);
            mma8(acc[0][0], a0[0], a0[1], a0[2], a0[3], b0[0], b0[1]);
            mma8(acc[0][1], a0[0], a0[1], a0[2], a0[3], b0[2], b0[3]);
            mma8(acc[0][2], a0[0], a0[1], a0[2], a0[3], b1[0], b1[1]);
            mma8(acc[0][3], a0[0], a0[1], a0[2], a0[3], b1[2], b1[3]);
            mma8(acc[1][0], a1[0], a1[1], a1[2], a1[3], b0[0], b0[1]);
            mma8(acc[1][1], a1[0], a1[1], a1[2], a1[3], b0[2], b0[3]);
            mma8(acc[1][2], a1[0], a1[1], a1[2], a1[3], b1[0], b1[1]);
            mma8(acc[1][3], a1[0], a1[1], a1[2], a1[3], b1[2], b1[3]);
        }
        if (more) __syncthreads();
    }

    if (col0 < split) {
        // fp16 row-major write to C1; q columns pre-scaled by QSCALE_C
#pragma unroll
        for (int j = 0; j < 4; ++j) {
            const int c = col0 + wn + j * 8 + 2 * tig;
            float2 bj = *(const float2*)&bias[c];
            const float sc = (c < qscale_end) ? QSCALE_C : 1.0f;
#pragma unroll
            for (int i = 0; i < 2; ++i) {
                const int r0 = row0 + wm + i * 16 + gid;
                *(uint32_t*)&C1[(size_t)r0 * ldc1 + c] =
                    pack_f16((acc[i][j][0] + bj.x) * sc, (acc[i][j][1] + bj.y) * sc);
                *(uint32_t*)&C1[(size_t)(r0 + 8) * ldc1 + c] =
                    pack_f16((acc[i][j][2] + bj.x) * sc, (acc[i][j][3] + bj.y) * sc);
            }
        }
    } else {
        // fp16 transposed write: Ct[(b*512 + (c - split)) * SEQ + l]
        const int bb = row0 >> 11;
        const int lb = row0 & 2047;
#pragma unroll
        for (int j = 0; j < 4; ++j) {
            const int c = col0 + wn + j * 8 + 2 * tig;
            float2 bj = *(const float2*)&bias[c];
            __half* o0 = Ct + ((size_t)(bb * 512 + (c - split))) * SEQ;
            __half* o1 = o0 + SEQ;
#pragma unroll
            for (int i = 0; i < 2; ++i) {
                const int l0 = lb + wm + i * 16 + gid;
                o0[l0]     = __float2half_rn(acc[i][j][0] + bj.x);
                o1[l0]     = __float2half_rn(acc[i][j][1] + bj.y);
                o0[l0 + 8] = __float2half_rn(acc[i][j][2] + bj.x);
                o1[l0 + 8] = __float2half_rn(acc[i][j][3] + bj.y);
            }
        }
    }
}

// ---------------- MoE grouped GEMM (gather rows), WT is [E][N][K] -----------
#define MOE_SMEM GEMM_SMEM

template<bool GELU, bool RESID>
__global__ void __launch_bounds__(256) gemm_moe(
    const float* __restrict__ X, const float* __restrict__ WT,
    const float* __restrict__ bias, const float* __restrict__ resid,
    float* __restrict__ Y, int K, int N)
{
    const int e = blockIdx.y >> 6;
    const int tile = blockIdx.y & 63;
    const int cnt = g_cnt[e];
    if (tile * 128 >= cnt) return;

    extern __shared__ uint32_t dsm[];
    uint32_t* As = dsm;
    uint32_t* Bs = dsm + 2 * G_ASTG;
    __shared__ int rows[128];
    const int t = threadIdx.x;
    if (t < 128) {
        int gi = tile * 128 + t;
        rows[t] = (gi < cnt) ? g_list[e * NTOK + gi] : -1;
    }
    __syncthreads();

    const int lane = t & 31, wid = t >> 5;
    const int gid = lane >> 2, tig = lane & 3;
    const int wm = (wid & 3) * 32, wn = (wid >> 2) * 32;
    const int col0 = blockIdx.x * 64;
    const float* We = WT + (size_t)e * K * N;
    const int lr = t >> 3, lc = (t & 7) * 4;

    const uint32_t as_st = smem_u32(As) + (uint32_t)((lr * 36 + lc) << 2);
    const uint32_t bs_st = smem_u32(Bs) + (uint32_t)((lr * 36 + lc) << 2);
    const uint32_t a_ld0 = smem_u32(As) + (uint32_t)((wm * 36) << 2) + a_lane_off(lane, 36);
    const uint32_t b_ld0 = smem_u32(Bs) + (uint32_t)((wn * 36) << 2) + b_lane_off(lane, 36);
    const uint32_t A_HALF = 16 * 36 * 4;

    int rws[4];
    bool rok[4];
#pragma unroll
    for (int p = 0; p < 4; ++p) {
        rws[p] = rows[lr + p * 32];
        rok[p] = rws[p] >= 0;
        if (!rok[p]) rws[p] = 0;
    }

    const int nIter = K >> 5;
#pragma unroll
    for (int p = 0; p < 4; ++p)
        cp16p(as_st + (uint32_t)(p * 32 * 36 * 4), &X[(size_t)rws[p] * K + lc], rok[p]);
#pragma unroll
    for (int p = 0; p < 2; ++p)
        cp16(bs_st + (uint32_t)(p * 32 * 36 * 4), &We[(size_t)(col0 + lr + p * 32) * K + lc]);
    CP_COMMIT();

    float acc[2][4][4] = {};
    for (int it = 0; it < nIter; ++it) {
        const int cur = it & 1;
        const bool more = (it + 1) < nIter;
        if (more) {
            const int k0 = (it + 1) << 5;
            const uint32_t so = (uint32_t)(((cur ^ 1) ? G_ASTG : 0) << 2);
            const uint32_t sb = (uint32_t)(((cur ^ 1) ? G_BSTG : 0) << 2);
#pragma unroll
            for (int p = 0; p < 4; ++p)
                cp16p(as_st + so + (uint32_t)(p * 32 * 36 * 4),
                      &X[(size_t)rws[p] * K + k0 + lc], rok[p]);
#pragma unroll
            for (int p = 0; p < 2; ++p)
                cp16(bs_st + sb + (uint32_t)(p * 32 * 36 * 4),
                     &We[(size_t)(col0 + lr + p * 32) * K + k0 + lc]);
            CP_COMMIT();
            CP_WAIT1();
        } else {
            CP_WAIT0();
        }
        __syncthreads();
        const uint32_t a_ld = a_ld0 + (uint32_t)((cur ? G_ASTG : 0) << 2);
        const uint32_t b_ld = b_ld0 + (uint32_t)((cur ? G_BSTG : 0) << 2);
#pragma unroll
        for (int s = 0; s < 4; ++s) {
            uint32_t a0[4], a1[4], b0[4], b1[4];
            ldsm4(a0[0], a0[1], a0[2], a0[3], a_ld + s * 32);
            ldsm4(a1[0], a1[1], a1[2], a1[3], a_ld + s * 32 + A_HALF);
            ldsm4(b0[0], b0[1], b0[2], b0[3], b_ld + s * 32);
            ldsm4(b1[0], b1[1], b1[2], b1[3], b_ld + s * 32 + A_HALF);
            mma8(acc[0][0], a0[0], a0[1], a0[2], a0[3], b0[0], b0[1]);
            mma8(acc[0][1], a0[0], a0[1], a0[2], a0[3], b0[2], b0[3]);
            mma8(acc[0][2], a0[0], a0[1], a0[2], a0[3], b1[0], b1[1]);
            mma8(acc[0][3], a0[0], a0[1], a0[2], a0[3], b1[2], b1[3]);
            mma8(acc[1][0], a1[0], a1[1], a1[2], a1[3], b0[0], b0[1]);
            mma8(acc[1][1], a1[0], a1[1], a1[2], a1[3], b0[2], b0[3]);
            mma8(acc[1][2], a1[0], a1[1], a1[2], a1[3], b1[0], b1[1]);
            mma8(acc[1][3], a1[0], a1[1], a1[2], a1[3], b1[2], b1[3]);
        }
        if (more) __syncthreads();
    }

#pragma unroll
    for (int j = 0; j < 4; ++j) {
        const int c = col0 + wn + j * 8 + 2 * tig;
        float2 bj = *(const float2*)&bias[(size_t)e * N + c];
#pragma unroll
        for (int i = 0; i < 2; ++i) {
#pragma unroll
            for (int h = 0; h < 2; ++h) {
                const int m = wm + i * 16 + gid + h * 8;
                const int tok = rows[m];
                if (tok < 0) continue;
                float v0 = acc[i][j][h * 2 + 0] + bj.x;
                float v1 = acc[i][j][h * 2 + 1] + bj.y;
                if (GELU) {
                    v0 = 0.5f * v0 * (1.f + erff(v0 * 0.70710678118654752f));
                    v1 = 0.5f * v1 * (1.f + erff(v1 * 0.70710678118654752f));
                }
                if (RESID) {
                    float2 q = *(const float2*)&resid[(size_t)tok * N + c];
                    v0 += q.x; v1 += q.y;
                }
                *(float2*)&Y[(size_t)tok * N + c] = make_float2(v0, v1);
            }
        }
    }
}

// ---------------- flash attention: all-fp16 operands, log2 softmax ----------
// smem rows all 144B (128B data + 16B pad):
//   Ks[2][64 rows], Vs[2][64 rows], Qs[128 rows], Ps[128 rows]  = 72 KB
#define FL_KSTG_W 2304               // words per K/V buffer (64*144/4)
#define FL_Q_OFF  (4 * FL_KSTG_W)    // 9216 words
#define FL_P_OFF  (FL_Q_OFF + 4608)  // + 128*144/4
#define FLASH_SMEM ((FL_P_OFF + 4608) * 4)   // 73728 B

__global__ void __launch_bounds__(256, 3) flash_attn(
    const __half* __restrict__ qb, int qs,
    const __half* __restrict__ kb, int kstr,
    const __half* __restrict__ vtb,
    float* __restrict__ out, int Lk)
{
    extern __shared__ uint32_t sm[];
    uint32_t* Ks = sm;
    uint32_t* Vs = sm + 2 * FL_KSTG_W;
    uint32_t* Qs = sm + FL_Q_OFF;
    uint32_t* Ps = sm + FL_P_OFF;

    const int t = threadIdx.x;
    const int lane = t & 31, wid = t >> 5;
    const int gid = lane >> 2, tig = lane & 3;
    const int m0 = wid * 16;
    const int b = blockIdx.x >> 3;
    const int h = blockIdx.x & 7;
    const int q0 = b * SEQ + blockIdx.y * 128;
    const int kbase = b * Lk;
    const int hoff = h * HDIM;
    const __half* vrow = vtb + ((size_t)(b * DMODEL + hoff)) * SEQ;

    const uint32_t qs_base = smem_u32(Qs);
    const uint32_t ks_base = smem_u32(Ks);
    const uint32_t vs_base = smem_u32(Vs);
    const uint32_t ps_base = smem_u32(Ps);
    // fp16 A-fragment lane offset (144B row stride)
    const uint32_t ap_off = (uint32_t)((lane & 15) * 144 + ((lane >> 4) << 4));
    const uint32_t q_ld = qs_base + (uint32_t)(m0 * 144) + ap_off;
    const uint32_t p_ld = ps_base + (uint32_t)(m0 * 144) + ap_off;
    // fp16 B-fragment lane offset (n-major, 144B row stride)
    const uint32_t b_off = (uint32_t)(((lane & 7) + ((lane >> 4) << 3)) * 144 +
                                      (((lane >> 3) & 1) << 4));

    // group 0: Q fp16 (128 rows x 8 chunks = 1024 chunks, 4 per thread)
#pragma unroll
    for (int p = 0; p < 4; ++p) {
        const int id = t + p * 256, r = id >> 3, c16 = id & 7;
        cp16(qs_base + (uint32_t)(r * 144 + c16 * 16),
             &qb[(size_t)(q0 + r) * qs + hoff + c16 * 8]);
    }
    CP_COMMIT();
    // group 1: K/V tile 0 (each 64 rows x 8 chunks = 512 chunks, 2 per thread)
#pragma unroll
    for (int p = 0; p < 2; ++p) {
        const int id = t + p * 256, r = id >> 3, c16 = id & 7;
        cp16(ks_base + (uint32_t)(r * 144 + c16 * 16),
             &kb[(size_t)(kbase + r) * kstr + hoff + c16 * 8]);
        cp16(vs_base + (uint32_t)(r * 144 + c16 * 16),
             &vrow[(size_t)r * SEQ + c16 * 8]);
    }
    CP_COMMIT();
    CP_WAIT1();
    __syncthreads();

    // Q fragments (loop-invariant, pre-scaled by QSCALE_C at projection)
    uint32_t qa[4][4];
#pragma unroll
    for (int s4 = 0; s4 < 4; ++s4)
        ldsm4(qa[s4][0], qa[s4][1], qa[s4][2], qa[s4][3], q_ld + s4 * 32);

    float oacc[8][4] = {};
    float m_i[2] = {-1e30f, -1e30f};
    float l_i[2] = {0.f, 0.f};
    const int nT = Lk >> 6;

    for (int it = 0; it < nT; ++it) {
        CP_WAIT0();
        __syncthreads();
        if (it + 1 < nT) {
            const int kt2 = (it + 1) << 6;
            const uint32_t off = ((it + 1) & 1) ? (uint32_t)(FL_KSTG_W * 4) : 0u;
#pragma unroll
            for (int p = 0; p < 2; ++p) {
                const int id = t + p * 256, r = id >> 3, c16 = id & 7;
                cp16(ks_base + off + (uint32_t)(r * 144 + c16 * 16),
                     &kb[(size_t)(kbase + kt2 + r) * kstr + hoff + c16 * 8]);
                cp16(vs_base + off + (uint32_t)(r * 144 + c16 * 16),
                     &vrow[(size_t)r * SEQ + kt2 + c16 * 8]);
            }
            CP_COMMIT();
        }
        const uint32_t buf = (it & 1) ? (uint32_t)(FL_KSTG_W * 4) : 0u;
        const uint32_t k_ld = ks_base + buf + b_off;
        const uint32_t v_ld = vs_base + buf + b_off;

        // S = Q @ K^T (fp16 m16n8k16, 4 k-steps of 16 dims)
        float sacc[8][4] = {};
#pragma unroll
        for (int s4 = 0; s4 < 4; ++s4) {
#pragma unroll
            for (int g = 0; g < 4; ++g) {
                uint32_t bq[4];
                ldsm4(bq[0], bq[1], bq[2], bq[3],
                      k_ld + g * (16 * 144) + s4 * 32);
                mma16h(sacc[g * 2],     qa[s4][0], qa[s4][1], qa[s4][2], qa[s4][3],
                       bq[0], bq[1]);
                mma16h(sacc[g * 2 + 1], qa[s4][0], qa[s4][1], qa[s4][2], qa[s4][3],
                       bq[2], bq[3]);
            }
        }

        // stabilized online softmax in log2 domain
        float mr0 = -1e30f, mr1 = -1e30f;
#pragma unroll
        for (int nt = 0; nt < 8; ++nt) {
            mr0 = fmaxf(mr0, fmaxf(sacc[nt][0], sacc[nt][1]));
            mr1 = fmaxf(mr1, fmaxf(sacc[nt][2], sacc[nt][3]));
        }
        mr0 = fmaxf(mr0, __shfl_xor_sync(0xffffffffu, mr0, 1));
        mr0 = fmaxf(mr0, __shfl_xor_sync(0xffffffffu, mr0, 2));
        mr1 = fmaxf(mr1, __shfl_xor_sync(0xffffffffu, mr1, 1));
        mr1 = fmaxf(mr1, __shfl_xor_sync(0xffffffffu, mr1, 2));
        const float mn0 = fmaxf(m_i[0], mr0);
        const float mn1 = fmaxf(m_i[1], mr1);
        const float al0 = ex2(m_i[0] - mn0);
        const float al1 = ex2(m_i[1] - mn1);
        m_i[0] = mn0; m_i[1] = mn1;
        float rs0 = 0.f, rs1 = 0.f;
#pragma unroll
        for (int nt = 0; nt < 8; ++nt) {
            sacc[nt][0] = ex2(sacc[nt][0] - mn0);
            sacc[nt][1] = ex2(sacc[nt][1] - mn0);
            sacc[nt][2] = ex2(sacc[nt][2] - mn1);
            sacc[nt][3] = ex2(sacc[nt][3] - mn1);
            rs0 += sacc[nt][0] + sacc[nt][1];
            rs1 += sacc[nt][2] + sacc[nt][3];
        }
        rs0 += __shfl_xor_sync(0xffffffffu, rs0, 1);
        rs0 += __shfl_xor_sync(0xffffffffu, rs0, 2);
        rs1 += __shfl_xor_sync(0xffffffffu, rs1, 1);
        rs1 += __shfl_xor_sync(0xffffffffu, rs1, 2);
        l_i[0] = l_i[0] * al0 + rs0;
        l_i[1] = l_i[1] * al1 + rs1;
#pragma unroll
        for (int nt = 0; nt < 8; ++nt) {
            oacc[nt][0] *= al0; oacc[nt][1] *= al0;
            oacc[nt][2] *= al1; oacc[nt][3] *= al1;
        }

        // write P packed f16x2 — warp-private rows (word stride 36 = 144B)
#pragma unroll
        for (int nt = 0; nt < 8; ++nt) {
            const int wi = nt * 4 + tig;
            Ps[(m0 + gid) * 36 + wi]     = pack_f16(sacc[nt][0], sacc[nt][1]);
            Ps[(m0 + gid + 8) * 36 + wi] = pack_f16(sacc[nt][2], sacc[nt][3]);
        }
        __syncwarp();

        // O += P @ V (fp16 m16n8k16; 4 k-steps of 16 keys)
#pragma unroll
        for (int s4 = 0; s4 < 4; ++s4) {
            uint32_t a[4];
            ldsm4(a[0], a[1], a[2], a[3], p_ld + s4 * 32);
#pragma unroll
            for (int g = 0; g < 4; ++g) {
                uint32_t bv[4];
                ldsm4(bv[0], bv[1], bv[2], bv[3],
                      v_ld + g * (16 * 144) + s4 * 32);
                mma16h(oacc[g * 2],     a[0], a[1], a[2], a[3], bv[0], bv[1]);
                mma16h(oacc[g * 2 + 1], a[0], a[1], a[2], a[3], bv[2], bv[3]);
            }
        }
    }

    const float inv0 = 1.f / l_i[0];
    const float inv1 = 1.f / l_i[1];
    const int r0 = q0 + m0 + gid;
#pragma unroll
    for (int nt = 0; nt < 8; ++nt) {
        const int c = hoff + nt * 8 + 2 * tig;
        *(float2*)&out[(size_t)r0 * DMODEL + c] =
            make_float2(oacc[nt][0] * inv0, oacc[nt][1] * inv0);
        *(float2*)&out[(size_t)(r0 + 8) * DMODEL + c] =
            make_float2(oacc[nt][2] * inv1, oacc[nt][3] * inv1);
    }
}

// ---------------- LayerNorm over D=512 -------------------------------------
__global__ void __launch_bounds__(128) layernorm_k(
    const float* __restrict__ in, const float* __restrict__ g,
    const float* __restrict__ bt, float* __restrict__ out)
{
    const int row = blockIdx.x;
    const int t = threadIdx.x;
    float4 v = *reinterpret_cast<const float4*>(&in[(size_t)row * 512 + t * 4]);
    float s  = v.x + v.y + v.z + v.w;
    float s2 = v.x * v.x + v.y * v.y + v.z * v.z + v.w * v.w;
#pragma unroll
    for (int off = 16; off >= 1; off >>= 1) {
        s  += __shfl_xor_sync(0xffffffffu, s,  off);
        s2 += __shfl_xor_sync(0xffffffffu, s2, off);
    }
    __shared__ float sh[8];
    int w = t >> 5;
    if ((t & 31) == 0) { sh[w] = s; sh[w + 4] = s2; }
    __syncthreads();
    float ts  = sh[0] + sh[1] + sh[2] + sh[3];
    float ts2 = sh[4] + sh[5] + sh[6] + sh[7];
    float mu  = ts * (1.f / 512.f);
    float var = ts2 * (1.f / 512.f) - mu * mu;
    float inv = rsqrtf(var + 1e-5f);
    float4 gg = *reinterpret_cast<const float4*>(&g[t * 4]);
    float4 bb = *reinterpret_cast<const float4*>(&bt[t * 4]);
    float4 o;
    o.x = (v.x - mu) * inv * gg.x + bb.x;
    o.y = (v.y - mu) * inv * gg.y + bb.y;
    o.z = (v.z - mu) * inv * gg.z + bb.z;
    o.w = (v.w - mu) * inv * gg.w + bb.w;
    *reinterpret_cast<float4*>(&out[(size_t)row * 512 + t * 4]) = o;
}

// ---------------- gate: top-1 routing ---------------------------------------
__global__ void __launch_bounds__(256) gate_k(
    const float* __restrict__ x, const float* __restrict__ gw,
    const float* __restrict__ gb)
{
    int warp = threadIdx.x >> 5, lane = threadIdx.x & 31;
    int tok = blockIdx.x * 8 + warp;
    float s0 = 0, s1 = 0, s2 = 0, s3 = 0;
    const float* xr = &x[(size_t)tok * 512];
#pragma unroll
    for (int d = lane * 4; d < 512; d += 128) {
        float4 xv = *reinterpret_cast<const float4*>(&xr[d]);
        float4 w0 = *reinterpret_cast<const float4*>(&gw[d]);
        float4 w1 = *reinterpret_cast<const float4*>(&gw[512 + d]);
        float4 w2 = *reinterpret_cast<const float4*>(&gw[1024 + d]);
        float4 w3 = *reinterpret_cast<const float4*>(&gw[1536 + d]);
        s0 += xv.x * w0.x + xv.y * w0.y + xv.z * w0.z + xv.w * w0.w;
        s1 += xv.x * w1.x + xv.y * w1.y + xv.z * w1.z + xv.w * w1.w;
        s2 += xv.x * w2.x + xv.y * w2.y + xv.z * w2.z + xv.w * w2.w;
        s3 += xv.x * w3.x + xv.y * w3.y + xv.z * w3.z + xv.w * w3.w;
    }
#pragma unroll
    for (int off = 16; off >= 1; off >>= 1) {
        s0 += __shfl_xor_sync(0xffffffffu, s0, off);
        s1 += __shfl_xor_sync(0xffffffffu, s1, off);
        s2 += __shfl_xor_sync(0xffffffffu, s2, off);
        s3 += __shfl_xor_sync(0xffffffffu, s3, off);
    }
    if (lane == 0) {
        s0 += gb[0]; s1 += gb[1]; s2 += gb[2]; s3 += gb[3];
        int best = 0; float bv = s0;
        if (s1 > bv) { bv = s1; best = 1; }
        if (s2 > bv) { bv = s2; best = 2; }
        if (s3 > bv) { bv = s3; best = 3; }
        int pos = atomicAdd(&g_cnt[best], 1);
        g_list[best * NTOK + pos] = tok;
    }
}

// ---------------- launch ----------------------------------------------------
extern "C" void kernel_launch(void* const* d_in, const int* in_sizes, int n_in,
                              void* d_out, int out_size)
{
    const float* x        = (const float*)d_in[0];
    const float* memory   = (const float*)d_in[1];
    const float* sa_in_w  = (const float*)d_in[2];
    const float* sa_in_b  = (const float*)d_in[3];
    const float* sa_out_w = (const float*)d_in[4];
    const float* sa_out_b = (const float*)d_in[5];
    const float* ca_in_w  = (const float*)d_in[6];
    const float* ca_in_b  = (const float*)d_in[7];
    const float* ca_out_w = (const float*)d_in[8];
    const float* ca_out_b = (const float*)d_in[9];
    const float* gate_w   = (const float*)d_in[10];
    const float* gate_b   = (const float*)d_in[11];
    const float* w1       = (const float*)d_in[12];
    const float* b1       = (const float*)d_in[13];
    const float* w2       = (const float*)d_in[14];
    const float* b2       = (const float*)d_in[15];
    const float* ln1_g    = (const float*)d_in[16];
    const float* ln1_b    = (const float*)d_in[17];
    const float* ln2_g    = (const float*)d_in[18];
    const float* ln2_b    = (const float*)d_in[19];
    const float* ln3_g    = (const float*)d_in[20];
    const float* ln3_b    = (const float*)d_in[21];
    float* out = (float*)d_out;

    float *attn, *tmp, *x1, *x2, *hbuf, *w1t, *w2t;
    __half *qk, *vt;
    cudaGetSymbolAddress((void**)&qk,   g_qkv);
    cudaGetSymbolAddress((void**)&vt,   g_vt);
    cudaGetSymbolAddress((void**)&attn, g_attn);
    cudaGetSymbolAddress((void**)&tmp,  g_tmp);
    cudaGetSymbolAddress((void**)&x1,   g_x1);
    cudaGetSymbolAddress((void**)&x2,   g_x2);
    cudaGetSymbolAddress((void**)&hbuf, g_h);
    cudaGetSymbolAddress((void**)&w1t,  g_w1t);
    cudaGetSymbolAddress((void**)&w2t,  g_w2t);

    cudaFuncSetAttribute(flash_attn, cudaFuncAttributeMaxDynamicSharedMemorySize,
                         FLASH_SMEM);
    cudaFuncSetAttribute(gemm_nt, cudaFuncAttributeMaxDynamicSharedMemorySize,
                         GEMM_SMEM);
    cudaFuncSetAttribute(gemm_proj, cudaFuncAttributeMaxDynamicSharedMemorySize,
                         GEMM_SMEM);
    cudaFuncSetAttribute(gemm_moe<true, false>,
                         cudaFuncAttributeMaxDynamicSharedMemorySize, MOE_SMEM);
    cudaFuncSetAttribute(gemm_moe<false, true>,
                         cudaFuncAttributeMaxDynamicSharedMemorySize, MOE_SMEM);

    zero_cnt_kernel<<<1, 32>>>();
    transpose_k<<<dim3(64, 16, 4), dim3(32, 8)>>>(w1, w1t, 512, 2048);
    transpose_k<<<dim3(16, 64, 4), dim3(32, 8)>>>(w2, w2t, 2048, 512);

    // --- self-attention: fused q(scaled)/k (fp16 row-major) + v^T (fp16) ---
    gemm_proj<<<dim3(24, 64), 256, GEMM_SMEM>>>(x, sa_in_w, sa_in_b, qk, 1024,
                                                vt, NTOK, 1536, 512, 1024, 512);
    flash_attn<<<dim3(32, 16), 256, FLASH_SMEM>>>(qk, 1024, qk + 512, 1024, vt,
                                                  attn, SEQ);
    gemm_nt<<<dim3(8, 64), 256, GEMM_SMEM>>>(attn, sa_out_w, sa_out_b, x, tmp,
                                             NTOK, 512, 512);
    layernorm_k<<<NTOK, 128>>>(tmp, ln1_g, ln1_b, x1);

    // --- cross-attention ---
    // q from x1 (fp16, scaled), ld 512
    gemm_proj<<<dim3(8, 64), 256, GEMM_SMEM>>>(x1, ca_in_w, ca_in_b, qk, 512,
                                               vt, NTOK, 512, 512, 512, 512);
    // fused k (fp16, ld 512) + v^T (fp16) from memory
    gemm_proj<<<dim3(16, 64), 256, GEMM_SMEM>>>(memory, ca_in_w + 512 * 512,
                                                ca_in_b + 512,
                                                qk + (size_t)NTOK * 512, 512,
                                                vt, NTOK, 1024, 512, 512, 0);
    flash_attn<<<dim3(32, 16), 256, FLASH_SMEM>>>(qk, 512,
                                                  qk + (size_t)NTOK * 512, 512,
                                                  vt, attn, SEQ);
    gemm_nt<<<dim3(8, 64), 256, GEMM_SMEM>>>(attn, ca_out_w, ca_out_b, x1, tmp,
                                             NTOK, 512, 512);
    layernorm_k<<<NTOK, 128>>>(tmp, ln2_g, ln2_b, x2);

    // --- MoE FFN (top-1 routed) ---
    gate_k<<<NTOK / 8, 256>>>(x2, gate_w, gate_b);
    gemm_moe<true,  false><<<dim3(32, 256), 256, MOE_SMEM>>>(x2,   w1t, b1, nullptr,
                                                             hbuf, 512, 2048);
    gemm_moe<false, true ><<<dim3(8,  256), 256, MOE_SMEM>>>(hbuf, w2t, b2, x2,
                                                             tmp,  2048, 512);
    layernorm_k<<<NTOK, 128>>>(tmp, ln3_g, ln3_b, out);
}

// round 17
// speedup vs baseline: 1.2619x; 1.2619x over previous
#include <cuda_runtime.h>
#include <cuda_fp16.h>
#include <math.h>
#include <stdint.h>

#define NTOK 8192      // B * L = 4 * 2048
#define DMODEL 512
#define HDIM 64
#define FDIM 2048
#define NEXP 4
#define SEQ 2048

// ---------------- scratch (device globals; no allocation allowed) ----------
__device__ __half g_qkv[(size_t)NTOK * 1024];   // q/k projections (fp16)
__device__ __half g_vt[(size_t)NTOK * 512];     // V^T fp16
__device__ __half g_attnh[(size_t)NTOK * 512];  // attention output fp16
__device__ __half g_ah[(size_t)NTOK * 512];     // activation fp16 (x / x1 / x2)
__device__ __half g_bh[(size_t)NTOK * 512];     // memory fp16
__device__ __half g_hbuf[(size_t)NTOK * FDIM];  // MoE hidden fp16
__device__ float g_tmp[(size_t)NTOK * DMODEL];
__device__ float g_x1[(size_t)NTOK * DMODEL];
__device__ float g_x2[(size_t)NTOK * DMODEL];
__device__ __half g_wsain[1536 * 512];
__device__ __half g_wsaout[512 * 512];
__device__ __half g_wcain[1536 * 512];
__device__ __half g_wcaout[512 * 512];
__device__ __half g_w1t[(size_t)NEXP * FDIM * DMODEL];  // [E][2048][512]
__device__ __half g_w2t[(size_t)NEXP * DMODEL * FDIM];  // [E][512][2048]
__device__ int   g_cnt[NEXP];
__device__ int   g_list[NEXP * NTOK];

#define QSCALE_C 0.18033688011112042f   // 0.125 * log2(e)

__global__ void zero_cnt_kernel() {
    if (threadIdx.x < NEXP) g_cnt[threadIdx.x] = 0;
}

// ---------------- helpers ----------------------------------------------------
__device__ __forceinline__ void mma16h(float* c, uint32_t a0, uint32_t a1,
                                       uint32_t a2, uint32_t a3,
                                       uint32_t b0, uint32_t b1) {
    asm volatile(
        "mma.sync.aligned.m16n8k16.row.col.f32.f16.f16.f32 "
        "{%0,%1,%2,%3},{%4,%5,%6,%7},{%8,%9},{%0,%1,%2,%3};"
        : "+f"(c[0]), "+f"(c[1]), "+f"(c[2]), "+f"(c[3])
        : "r"(a0), "r"(a1), "r"(a2), "r"(a3), "r"(b0), "r"(b1));
}

__device__ __forceinline__ void ldsm4(uint32_t& r0, uint32_t& r1,
                                      uint32_t& r2, uint32_t& r3, uint32_t addr) {
    asm volatile("ldmatrix.sync.aligned.m8n8.x4.shared.b16 {%0,%1,%2,%3}, [%4];"
                 : "=r"(r0), "=r"(r1), "=r"(r2), "=r"(r3) : "r"(addr));
}

__device__ __forceinline__ uint32_t smem_u32(const void* p) {
    return (uint32_t)__cvta_generic_to_shared(p);
}

__device__ __forceinline__ void cp16(uint32_t s, const void* g) {
    asm volatile("cp.async.cg.shared.global [%0], [%1], 16;"
                 :: "r"(s), "l"(g));
}
__device__ __forceinline__ void cp16p(uint32_t s, const void* g, bool pred) {
    int sz = pred ? 16 : 0;
    asm volatile("cp.async.cg.shared.global [%0], [%1], 16, %2;"
                 :: "r"(s), "l"(g), "r"(sz));
}
#define CP_COMMIT() asm volatile("cp.async.commit_group;" ::: "memory")
#define CP_WAIT0()  asm volatile("cp.async.wait_group 0;" ::: "memory")
#define CP_WAIT1()  asm volatile("cp.async.wait_group 1;" ::: "memory")

__device__ __forceinline__ float ex2(float x) {
    float y;
    asm("ex2.approx.f32 %0, %1;" : "=f"(y) : "f"(x));
    return y;
}

__device__ __forceinline__ uint32_t pack_f16(float lo, float hi) {
    uint32_t r;
    asm("cvt.rn.f16x2.f32 %0, %1, %2;" : "=r"(r) : "f"(hi), "f"(lo));
    return r;
}

// fp16 fragment lane offsets (144B row stride; validated in flash)
__device__ __forceinline__ uint32_t h_a_off(int lane) {
    return (uint32_t)((lane & 15) * 144 + ((lane >> 4) << 4));
}
__device__ __forceinline__ uint32_t h_b_off(int lane) {
    return (uint32_t)(((lane & 7) + ((lane >> 4) << 3)) * 144 +
                      (((lane >> 3) & 1) << 4));
}

// ---------------- conversion kernels -----------------------------------------
__global__ void __launch_bounds__(256) cvt_h(
    const float* __restrict__ in, __half* __restrict__ out, int n)
{
    const int i = (blockIdx.x * 256 + threadIdx.x) * 4;
    if (i < n) {
        float4 v = *(const float4*)&in[i];
        *(uint32_t*)&out[i]     = pack_f16(v.x, v.y);
        *(uint32_t*)&out[i + 2] = pack_f16(v.z, v.w);
    }
}

// transpose fp32 -> fp16: in[z][R][C] -> out[z][C][R]
__global__ void __launch_bounds__(256) transpose_h(
    const float* __restrict__ in, __half* __restrict__ out, int R, int C)
{
    __shared__ float tile[32][33];
    const int bx = blockIdx.x * 32, by = blockIdx.y * 32;
    const float* src = in + (size_t)blockIdx.z * R * C;
    __half* dst = out + (size_t)blockIdx.z * R * C;
#pragma unroll
    for (int i = 0; i < 32; i += 8)
        tile[threadIdx.y + i][threadIdx.x] =
            src[(size_t)(by + threadIdx.y + i) * C + bx + threadIdx.x];
    __syncthreads();
#pragma unroll
    for (int i = 0; i < 32; i += 8)
        dst[(size_t)(bx + threadIdx.y + i) * R + by + threadIdx.x] =
            __float2half_rn(tile[threadIdx.x][threadIdx.y + i]);
}

// ---------------- fp16 GEMM constants ----------------------------------------
#define H_ASTG 18432u    // bytes per A stage: 128 rows * 144 B
#define H_BSTG 9216u     // bytes per B stage: 64 rows * 144 B
#define GEMMH_SMEM ((H_ASTG + H_BSTG) * 2)

// fp16 GEMM mainloop macro: expects A (fp16 [.,K]) rows row0.., B fp16 [N][K]
// rows col0..; leaves acc[2][4][4] filled. Uses 128x64 tile, K=64 per iter.
// (written inline in each kernel below)

// ---------------- GEMM: C[M,N] = A@B^T + bias (+resid), fp32 out ------------
__global__ void __launch_bounds__(256, 3) gemm_h(
    const __half* __restrict__ A, const __half* __restrict__ Bw,
    const float* __restrict__ bias, const float* __restrict__ resid,
    float* __restrict__ C, int M, int N, int K)
{
    extern __shared__ uint8_t dsm8[];
    const uint32_t as_base = smem_u32(dsm8);
    const uint32_t bs_base = as_base + 2 * H_ASTG;
    const int t = threadIdx.x;
    const int lane = t & 31, wid = t >> 5;
    const int gid = lane >> 2, tig = lane & 3;
    const int wm = (wid & 3) * 32, wn = (wid >> 2) * 32;
    const int row0 = blockIdx.y * 128, col0 = blockIdx.x * 64;
    const int lr = t >> 3, lc = t & 7;

    const int nIter = K >> 6;
#pragma unroll
    for (int p = 0; p < 4; ++p) {
        const int r = lr + p * 32;
        cp16(as_base + (uint32_t)(r * 144 + lc * 16),
             &A[(size_t)(row0 + r) * K + lc * 8]);
    }
#pragma unroll
    for (int p = 0; p < 2; ++p) {
        const int r = lr + p * 32;
        cp16(bs_base + (uint32_t)(r * 144 + lc * 16),
             &Bw[(size_t)(col0 + r) * K + lc * 8]);
    }
    CP_COMMIT();

    float acc[2][4][4] = {};
    for (int it = 0; it < nIter; ++it) {
        const int cur = it & 1;
        const bool more = (it + 1) < nIter;
        if (more) {
            const int k0 = (it + 1) << 6;
            const uint32_t ao = (cur ^ 1) ? H_ASTG : 0u;
            const uint32_t bo = (cur ^ 1) ? H_BSTG : 0u;
#pragma unroll
            for (int p = 0; p < 4; ++p) {
                const int r = lr + p * 32;
                cp16(as_base + ao + (uint32_t)(r * 144 + lc * 16),
                     &A[(size_t)(row0 + r) * K + k0 + lc * 8]);
            }
#pragma unroll
            for (int p = 0; p < 2; ++p) {
                const int r = lr + p * 32;
                cp16(bs_base + bo + (uint32_t)(r * 144 + lc * 16),
                     &Bw[(size_t)(col0 + r) * K + k0 + lc * 8]);
            }
            CP_COMMIT();
            CP_WAIT1();
        } else {
            CP_WAIT0();
        }
        __syncthreads();
        const uint32_t a_ld = as_base + (cur ? H_ASTG : 0u) +
                              (uint32_t)(wm * 144) + h_a_off(lane);
        const uint32_t b_ld = bs_base + (cur ? H_BSTG : 0u) +
                              (uint32_t)(wn * 144) + h_b_off(lane);
#pragma unroll
        for (int s4 = 0; s4 < 4; ++s4) {
            uint32_t a0[4], a1[4], q0[4], q1[4];
            ldsm4(a0[0], a0[1], a0[2], a0[3], a_ld + s4 * 32);
            ldsm4(a1[0], a1[1], a1[2], a1[3], a_ld + 16 * 144 + s4 * 32);
            ldsm4(q0[0], q0[1], q0[2], q0[3], b_ld + s4 * 32);
            ldsm4(q1[0], q1[1], q1[2], q1[3], b_ld + 16 * 144 + s4 * 32);
            mma16h(acc[0][0], a0[0], a0[1], a0[2], a0[3], q0[0], q0[1]);
            mma16h(acc[0][1], a0[0], a0[1], a0[2], a0[3], q0[2], q0[3]);
            mma16h(acc[0][2], a0[0], a0[1], a0[2], a0[3], q1[0], q1[1]);
            mma16h(acc[0][3], a0[0], a0[1], a0[2], a0[3], q1[2], q1[3]);
            mma16h(acc[1][0], a1[0], a1[1], a1[2], a1[3], q0[0], q0[1]);
            mma16h(acc[1][1], a1[0], a1[1], a1[2], a1[3], q0[2], q0[3]);
            mma16h(acc[1][2], a1[0], a1[1], a1[2], a1[3], q1[0], q1[1]);
            mma16h(acc[1][3], a1[0], a1[1], a1[2], a1[3], q1[2], q1[3]);
        }
        if (more) __syncthreads();
    }

#pragma unroll
    for (int j = 0; j < 4; ++j) {
        const int c = col0 + wn + j * 8 + 2 * tig;
        float2 bj = *(const float2*)&bias[c];
#pragma unroll
        for (int i = 0; i < 2; ++i) {
            const int r0 = row0 + wm + i * 16 + gid;
            float2 v0 = make_float2(acc[i][j][0] + bj.x, acc[i][j][1] + bj.y);
            float2 v1 = make_float2(acc[i][j][2] + bj.x, acc[i][j][3] + bj.y);
            if (resid) {
                float2 p0 = *(const float2*)&resid[(size_t)r0 * N + c];
                float2 p1 = *(const float2*)&resid[(size_t)(r0 + 8) * N + c];
                v0.x += p0.x; v0.y += p0.y; v1.x += p1.x; v1.y += p1.y;
            }
            *(float2*)&C[(size_t)r0 * N + c] = v0;
            *(float2*)&C[(size_t)(r0 + 8) * N + c] = v1;
        }
    }
}

// ---------------- fused projection GEMM, fp16 in/out ------------------------
// cols < split: C1 fp16 row-major (ld ldc1), cols < qscale_end scaled QSCALE_C
// cols >= split: Ct fp16 transposed [(b*512 + c-split)*SEQ + l]
__global__ void __launch_bounds__(256, 3) gemm_projh(
    const __half* __restrict__ A, const __half* __restrict__ Bw,
    const float* __restrict__ bias, __half* __restrict__ C1, int ldc1,
    __half* __restrict__ Ct, int M, int N, int K, int split, int qscale_end)
{
    extern __shared__ uint8_t dsm8[];
    const uint32_t as_base = smem_u32(dsm8);
    const uint32_t bs_base = as_base + 2 * H_ASTG;
    const int t = threadIdx.x;
    const int lane = t & 31, wid = t >> 5;
    const int gid = lane >> 2, tig = lane & 3;
    const int wm = (wid & 3) * 32, wn = (wid >> 2) * 32;
    const int row0 = blockIdx.y * 128, col0 = blockIdx.x * 64;
    const int lr = t >> 3, lc = t & 7;

    const int nIter = K >> 6;
#pragma unroll
    for (int p = 0; p < 4; ++p) {
        const int r = lr + p * 32;
        cp16(as_base + (uint32_t)(r * 144 + lc * 16),
             &A[(size_t)(row0 + r) * K + lc * 8]);
    }
#pragma unroll
    for (int p = 0; p < 2; ++p) {
        const int r = lr + p * 32;
        cp16(bs_base + (uint32_t)(r * 144 + lc * 16),
             &Bw[(size_t)(col0 + r) * K + lc * 8]);
    }
    CP_COMMIT();

    float acc[2][4][4] = {};
    for (int it = 0; it < nIter; ++it) {
        const int cur = it & 1;
        const bool more = (it + 1) < nIter;
        if (more) {
            const int k0 = (it + 1) << 6;
            const uint32_t ao = (cur ^ 1) ? H_ASTG : 0u;
            const uint32_t bo = (cur ^ 1) ? H_BSTG : 0u;
#pragma unroll
            for (int p = 0; p < 4; ++p) {
                const int r = lr + p * 32;
                cp16(as_base + ao + (uint32_t)(r * 144 + lc * 16),
                     &A[(size_t)(row0 + r) * K + k0 + lc * 8]);
            }
#pragma unroll
            for (int p = 0; p < 2; ++p) {
                const int r = lr + p * 32;
                cp16(bs_base + bo + (uint32_t)(r * 144 + lc * 16),
                     &Bw[(size_t)(col0 + r) * K + k0 + lc * 8]);
            }
            CP_COMMIT();
            CP_WAIT1();
        } else {
            CP_WAIT0();
        }
        __syncthreads();
        const uint32_t a_ld = as_base + (cur ? H_ASTG : 0u) +
                              (uint32_t)(wm * 144) + h_a_off(lane);
        const uint32_t b_ld = bs_base + (cur ? H_BSTG : 0u) +
                              (uint32_t)(wn * 144) + h_b_off(lane);
#pragma unroll
        for (int s4 = 0; s4 < 4; ++s4) {
            uint32_t a0[4], a1[4], q0[4], q1[4];
            ldsm4(a0[0], a0[1], a0[2], a0[3], a_ld + s4 * 32);
            ldsm4(a1[0], a1[1], a1[2], a1[3], a_ld + 16 * 144 + s4 * 32);
            ldsm4(q0[0], q0[1], q0[2], q0[3], b_ld + s4 * 32);
            ldsm4(q1[0], q1[1], q1[2], q1[3], b_ld + 16 * 144 + s4 * 32);
            mma16h(acc[0][0], a0[0], a0[1], a0[2], a0[3], q0[0], q0[1]);
            mma16h(acc[0][1], a0[0], a0[1], a0[2], a0[3], q0[2], q0[3]);
            mma16h(acc[0][2], a0[0], a0[1], a0[2], a0[3], q1[0], q1[1]);
            mma16h(acc[0][3], a0[0], a0[1], a0[2], a0[3], q1[2], q1[3]);
            mma16h(acc[1][0], a1[0], a1[1], a1[2], a1[3], q0[0], q0[1]);
            mma16h(acc[1][1], a1[0], a1[1], a1[2], a1[3], q0[2], q0[3]);
            mma16h(acc[1][2], a1[0], a1[1], a1[2], a1[3], q1[0], q1[1]);
            mma16h(acc[1][3], a1[0], a1[1], a1[2], a1[3], q1[2], q1[3]);
        }
        if (more) __syncthreads();
    }

    if (col0 < split) {
#pragma unroll
        for (int j = 0; j < 4; ++j) {
            const int c = col0 + wn + j * 8 + 2 * tig;
            float2 bj = *(const float2*)&bias[c];
            const float sc = (c < qscale_end) ? QSCALE_C : 1.0f;
#pragma unroll
            for (int i = 0; i < 2; ++i) {
                const int r0 = row0 + wm + i * 16 + gid;
                *(uint32_t*)&C1[(size_t)r0 * ldc1 + c] =
                    pack_f16((acc[i][j][0] + bj.x) * sc, (acc[i][j][1] + bj.y) * sc);
                *(uint32_t*)&C1[(size_t)(r0 + 8) * ldc1 + c] =
                    pack_f16((acc[i][j][2] + bj.x) * sc, (acc[i][j][3] + bj.y) * sc);
            }
        }
    } else {
        const int bb = row0 >> 11;
        const int lb = row0 & 2047;
#pragma unroll
        for (int j = 0; j < 4; ++j) {
            const int c = col0 + wn + j * 8 + 2 * tig;
            float2 bj = *(const float2*)&bias[c];
            __half* o0 = Ct + ((size_t)(bb * 512 + (c - split))) * SEQ;
            __half* o1 = o0 + SEQ;
#pragma unroll
            for (int i = 0; i < 2; ++i) {
                const int l0 = lb + wm + i * 16 + gid;
                o0[l0]     = __float2half_rn(acc[i][j][0] + bj.x);
                o1[l0]     = __float2half_rn(acc[i][j][1] + bj.y);
                o0[l0 + 8] = __float2half_rn(acc[i][j][2] + bj.x);
                o1[l0 + 8] = __float2half_rn(acc[i][j][3] + bj.y);
            }
        }
    }
}

// ---------------- MoE grouped GEMM, fp16 in; out fp16 (GELU) or fp32+resid --
template<bool GELU, bool RESID>
__global__ void __launch_bounds__(256, 3) gemm_moeh(
    const __half* __restrict__ X, const __half* __restrict__ WT,
    const float* __restrict__ bias, const float* __restrict__ resid,
    __half* __restrict__ Yh, float* __restrict__ Yf, int K, int N)
{
    const int e = blockIdx.y >> 6;
    const int tile = blockIdx.y & 63;
    const int cnt = g_cnt[e];
    if (tile * 128 >= cnt) return;

    extern __shared__ uint8_t dsm8[];
    const uint32_t as_base = smem_u32(dsm8);
    const uint32_t bs_base = as_base + 2 * H_ASTG;
    __shared__ int rows[128];
    const int t = threadIdx.x;
    if (t < 128) {
        int gi = tile * 128 + t;
        rows[t] = (gi < cnt) ? g_list[e * NTOK + gi] : -1;
    }
    __syncthreads();

    const int lane = t & 31, wid = t >> 5;
    const int gid = lane >> 2, tig = lane & 3;
    const int wm = (wid & 3) * 32, wn = (wid >> 2) * 32;
    const int col0 = blockIdx.x * 64;
    const __half* We = WT + (size_t)e * K * N;
    const int lr = t >> 3, lc = t & 7;

    int rws[4];
    bool rok[4];
#pragma unroll
    for (int p = 0; p < 4; ++p) {
        rws[p] = rows[lr + p * 32];
        rok[p] = rws[p] >= 0;
        if (!rok[p]) rws[p] = 0;
    }

    const int nIter = K >> 6;
#pragma unroll
    for (int p = 0; p < 4; ++p) {
        const int r = lr + p * 32;
        cp16p(as_base + (uint32_t)(r * 144 + lc * 16),
              &X[(size_t)rws[p] * K + lc * 8], rok[p]);
    }
#pragma unroll
    for (int p = 0; p < 2; ++p) {
        const int r = lr + p * 32;
        cp16(bs_base + (uint32_t)(r * 144 + lc * 16),
             &We[(size_t)(col0 + r) * K + lc * 8]);
    }
    CP_COMMIT();

    float acc[2][4][4] = {};
    for (int it = 0; it < nIter; ++it) {
        const int cur = it & 1;
        const bool more = (it + 1) < nIter;
        if (more) {
            const int k0 = (it + 1) << 6;
            const uint32_t ao = (cur ^ 1) ? H_ASTG : 0u;
            const uint32_t bo = (cur ^ 1) ? H_BSTG : 0u;
#pragma unroll
            for (int p = 0; p < 4; ++p) {
                const int r = lr + p * 32;
                cp16p(as_base + ao + (uint32_t)(r * 144 + lc * 16),
                      &X[(size_t)rws[p] * K + k0 + lc * 8], rok[p]);
            }
#pragma unroll
            for (int p = 0; p < 2; ++p) {
                const int r = lr + p * 32;
                cp16(bs_base + bo + (uint32_t)(r * 144 + lc * 16),
                     &We[(size_t)(col0 + r) * K + k0 + lc * 8]);
            }
            CP_COMMIT();
            CP_WAIT1();
        } else {
            CP_WAIT0();
        }
        __syncthreads();
        const uint32_t a_ld = as_base + (cur ? H_ASTG : 0u) +
                              (uint32_t)(wm * 144) + h_a_off(lane);
        const uint32_t b_ld = bs_base + (cur ? H_BSTG : 0u) +
                              (uint32_t)(wn * 144) + h_b_off(lane);
#pragma unroll
        for (int s4 = 0; s4 < 4; ++s4) {
            uint32_t a0[4], a1[4], q0[4], q1[4];
            ldsm4(a0[0], a0[1], a0[2], a0[3], a_ld + s4 * 32);
            ldsm4(a1[0], a1[1], a1[2], a1[3], a_ld + 16 * 144 + s4 * 32);
            ldsm4(q0[0], q0[1], q0[2], q0[3], b_ld + s4 * 32);
            ldsm4(q1[0], q1[1], q1[2], q1[3], b_ld + 16 * 144 + s4 * 32);
            mma16h(acc[0][0], a0[0], a0[1], a0[2], a0[3], q0[0], q0[1]);
            mma16h(acc[0][1], a0[0], a0[1], a0[2], a0[3], q0[2], q0[3]);
            mma16h(acc[0][2], a0[0], a0[1], a0[2], a0[3], q1[0], q1[1]);
            mma16h(acc[0][3], a0[0], a0[1], a0[2], a0[3], q1[2], q1[3]);
            mma16h(acc[1][0], a1[0], a1[1], a1[2], a1[3], q0[0], q0[1]);
            mma16h(acc[1][1], a1[0], a1[1], a1[2], a1[3], q0[2], q0[3]);
            mma16h(acc[1][2], a1[0], a1[1], a1[2], a1[3], q1[0], q1[1]);
            mma16h(acc[1][3], a1[0], a1[1], a1[2], a1[3], q1[2], q1[3]);
        }
        if (more) __syncthreads();
    }

#pragma unroll
    for (int j = 0; j < 4; ++j) {
        const int c = col0 + wn + j * 8 + 2 * tig;
        float2 bj = *(const float2*)&bias[(size_t)e * N + c];
#pragma unroll
        for (int i = 0; i < 2; ++i) {
#pragma unroll
            for (int h = 0; h < 2; ++h) {
                const int m = wm + i * 16 + gid + h * 8;
                const int tok = rows[m];
                if (tok < 0) continue;
                float v0 = acc[i][j][h * 2 + 0] + bj.x;
                float v1 = acc[i][j][h * 2 + 1] + bj.y;
                if (GELU) {
                    v0 = 0.5f * v0 * (1.f + erff(v0 * 0.70710678118654752f));
                    v1 = 0.5f * v1 * (1.f + erff(v1 * 0.70710678118654752f));
                    *(uint32_t*)&Yh[(size_t)tok * N + c] = pack_f16(v0, v1);
                } else {
                    if (RESID) {
                        float2 q = *(const float2*)&resid[(size_t)tok * N + c];
                        v0 += q.x; v1 += q.y;
                    }
                    *(float2*)&Yf[(size_t)tok * N + c] = make_float2(v0, v1);
                }
            }
        }
    }
}

// ---------------- flash attention: all-fp16, log2 softmax, fp16 out ---------
#define FL_KSTG_W 2304
#define FL_Q_OFF  (4 * FL_KSTG_W)
#define FL_P_OFF  (FL_Q_OFF + 4608)
#define FLASH_SMEM ((FL_P_OFF + 4608) * 4)

__global__ void __launch_bounds__(256, 3) flash_attn(
    const __half* __restrict__ qb, int qs,
    const __half* __restrict__ kb, int kstr,
    const __half* __restrict__ vtb,
    __half* __restrict__ out, int Lk)
{
    extern __shared__ uint32_t sm[];
    uint32_t* Ks = sm;
    uint32_t* Vs = sm + 2 * FL_KSTG_W;
    uint32_t* Qs = sm + FL_Q_OFF;
    uint32_t* Ps = sm + FL_P_OFF;

    const int t = threadIdx.x;
    const int lane = t & 31, wid = t >> 5;
    const int gid = lane >> 2, tig = lane & 3;
    const int m0 = wid * 16;
    const int b = blockIdx.x >> 3;
    const int h = blockIdx.x & 7;
    const int q0 = b * SEQ + blockIdx.y * 128;
    const int kbase = b * Lk;
    const int hoff = h * HDIM;
    const __half* vrow = vtb + ((size_t)(b * DMODEL + hoff)) * SEQ;

    const uint32_t qs_base = smem_u32(Qs);
    const uint32_t ks_base = smem_u32(Ks);
    const uint32_t vs_base = smem_u32(Vs);
    const uint32_t ps_base = smem_u32(Ps);
    const uint32_t ap_off = h_a_off(lane);
    const uint32_t q_ld = qs_base + (uint32_t)(m0 * 144) + ap_off;
    const uint32_t p_ld = ps_base + (uint32_t)(m0 * 144) + ap_off;
    const uint32_t b_off = h_b_off(lane);

#pragma unroll
    for (int p = 0; p < 4; ++p) {
        const int id = t + p * 256, r = id >> 3, c16 = id & 7;
        cp16(qs_base + (uint32_t)(r * 144 + c16 * 16),
             &qb[(size_t)(q0 + r) * qs + hoff + c16 * 8]);
    }
    CP_COMMIT();
#pragma unroll
    for (int p = 0; p < 2; ++p) {
        const int id = t + p * 256, r = id >> 3, c16 = id & 7;
        cp16(ks_base + (uint32_t)(r * 144 + c16 * 16),
             &kb[(size_t)(kbase + r) * kstr + hoff + c16 * 8]);
        cp16(vs_base + (uint32_t)(r * 144 + c16 * 16),
             &vrow[(size_t)r * SEQ + c16 * 8]);
    }
    CP_COMMIT();
    CP_WAIT1();
    __syncthreads();

    uint32_t qa[4][4];
#pragma unroll
    for (int s4 = 0; s4 < 4; ++s4)
        ldsm4(qa[s4][0], qa[s4][1], qa[s4][2], qa[s4][3], q_ld + s4 * 32);

    float oacc[8][4] = {};
    float m_i[2] = {-1e30f, -1e30f};
    float l_i[2] = {0.f, 0.f};
    const int nT = Lk >> 6;

    for (int it = 0; it < nT; ++it) {
        CP_WAIT0();
        __syncthreads();
        if (it + 1 < nT) {
            const int kt2 = (it + 1) << 6;
            const uint32_t off = ((it + 1) & 1) ? (uint32_t)(FL_KSTG_W * 4) : 0u;
#pragma unroll
            for (int p = 0; p < 2; ++p) {
                const int id = t + p * 256, r = id >> 3, c16 = id & 7;
                cp16(ks_base + off + (uint32_t)(r * 144 + c16 * 16),
                     &kb[(size_t)(kbase + kt2 + r) * kstr + hoff + c16 * 8]);
                cp16(vs_base + off + (uint32_t)(r * 144 + c16 * 16),
                     &vrow[(size_t)r * SEQ + kt2 + c16 * 8]);
            }
            CP_COMMIT();
        }
        const uint32_t buf = (it & 1) ? (uint32_t)(FL_KSTG_W * 4) : 0u;
        const uint32_t k_ld = ks_base + buf + b_off;
        const uint32_t v_ld = vs_base + buf + b_off;

        float sacc[8][4] = {};
#pragma unroll
        for (int s4 = 0; s4 < 4; ++s4) {
#pragma unroll
            for (int g = 0; g < 4; ++g) {
                uint32_t bq[4];
                ldsm4(bq[0], bq[1], bq[2], bq[3],
                      k_ld + g * (16 * 144) + s4 * 32);
                mma16h(sacc[g * 2],     qa[s4][0], qa[s4][1], qa[s4][2], qa[s4][3],
                       bq[0], bq[1]);
                mma16h(sacc[g * 2 + 1], qa[s4][0], qa[s4][1], qa[s4][2], qa[s4][3],
                       bq[2], bq[3]);
            }
        }

        float mr0 = -1e30f, mr1 = -1e30f;
#pragma unroll
        for (int nt = 0; nt < 8; ++nt) {
            mr0 = fmaxf(mr0, fmaxf(sacc[nt][0], sacc[nt][1]));
            mr1 = fmaxf(mr1, fmaxf(sacc[nt][2], sacc[nt][3]));
        }
        mr0 = fmaxf(mr0, __shfl_xor_sync(0xffffffffu, mr0, 1));
        mr0 = fmaxf(mr0, __shfl_xor_sync(0xffffffffu, mr0, 2));
        mr1 = fmaxf(mr1, __shfl_xor_sync(0xffffffffu, mr1, 1));
        mr1 = fmaxf(mr1, __shfl_xor_sync(0xffffffffu, mr1, 2));
        const float mn0 = fmaxf(m_i[0], mr0);
        const float mn1 = fmaxf(m_i[1], mr1);
        const float al0 = ex2(m_i[0] - mn0);
        const float al1 = ex2(m_i[1] - mn1);
        m_i[0] = mn0; m_i[1] = mn1;
        float rs0 = 0.f, rs1 = 0.f;
#pragma unroll
        for (int nt = 0; nt < 8; ++nt) {
            sacc[nt][0] = ex2(sacc[nt][0] - mn0);
            sacc[nt][1] = ex2(sacc[nt][1] - mn0);
            sacc[nt][2] = ex2(sacc[nt][2] - mn1);
            sacc[nt][3] = ex2(sacc[nt][3] - mn1);
            rs0 += sacc[nt][0] + sacc[nt][1];
            rs1 += sacc[nt][2] + sacc[nt][3];
        }
        rs0 += __shfl_xor_sync(0xffffffffu, rs0, 1);
        rs0 += __shfl_xor_sync(0xffffffffu, rs0, 2);
        rs1 += __shfl_xor_sync(0xffffffffu, rs1, 1);
        rs1 += __shfl_xor_sync(0xffffffffu, rs1, 2);
        l_i[0] = l_i[0] * al0 + rs0;
        l_i[1] = l_i[1] * al1 + rs1;
#pragma unroll
        for (int nt = 0; nt < 8; ++nt) {
            oacc[nt][0] *= al0; oacc[nt][1] *= al0;
            oacc[nt][2] *= al1; oacc[nt][3] *= al1;
        }

#pragma unroll
        for (int nt = 0; nt < 8; ++nt) {
            const int wi = nt * 4 + tig;
            Ps[(m0 + gid) * 36 + wi]     = pack_f16(sacc[nt][0], sacc[nt][1]);
            Ps[(m0 + gid + 8) * 36 + wi] = pack_f16(sacc[nt][2], sacc[nt][3]);
        }
        __syncwarp();

#pragma unroll
        for (int s4 = 0; s4 < 4; ++s4) {
            uint32_t a[4];
            ldsm4(a[0], a[1], a[2], a[3], p_ld + s4 * 32);
#pragma unroll
            for (int g = 0; g < 4; ++g) {
                uint32_t bv[4];
                ldsm4(bv[0], bv[1], bv[2], bv[3],
                      v_ld + g * (16 * 144) + s4 * 32);
                mma16h(oacc[g * 2],     a[0], a[1], a[2], a[3], bv[0], bv[1]);
                mma16h(oacc[g * 2 + 1], a[0], a[1], a[2], a[3], bv[2], bv[3]);
            }
        }
    }

    const float inv0 = 1.f / l_i[0];
    const float inv1 = 1.f / l_i[1];
    const int r0 = q0 + m0 + gid;
#pragma unroll
    for (int nt = 0; nt < 8; ++nt) {
        const int c = hoff + nt * 8 + 2 * tig;
        *(uint32_t*)&out[(size_t)r0 * DMODEL + c] =
            pack_f16(oacc[nt][0] * inv0, oacc[nt][1] * inv0);
        *(uint32_t*)&out[(size_t)(r0 + 8) * DMODEL + c] =
            pack_f16(oacc[nt][2] * inv1, oacc[nt][3] * inv1);
    }
}

// ---------------- LayerNorm: fp32 out + optional fp16 copy ------------------
__global__ void __launch_bounds__(128) layernorm_k(
    const float* __restrict__ in, const float* __restrict__ g,
    const float* __restrict__ bt, float* __restrict__ out,
    __half* __restrict__ outh)
{
    const int row = blockIdx.x;
    const int t = threadIdx.x;
    float4 v = *reinterpret_cast<const float4*>(&in[(size_t)row * 512 + t * 4]);
    float s  = v.x + v.y + v.z + v.w;
    float s2 = v.x * v.x + v.y * v.y + v.z * v.z + v.w * v.w;
#pragma unroll
    for (int off = 16; off >= 1; off >>= 1) {
        s  += __shfl_xor_sync(0xffffffffu, s,  off);
        s2 += __shfl_xor_sync(0xffffffffu, s2, off);
    }
    __shared__ float sh[8];
    int w = t >> 5;
    if ((t & 31) == 0) { sh[w] = s; sh[w + 4] = s2; }
    __syncthreads();
    float ts  = sh[0] + sh[1] + sh[2] + sh[3];
    float ts2 = sh[4] + sh[5] + sh[6] + sh[7];
    float mu  = ts * (1.f / 512.f);
    float var = ts2 * (1.f / 512.f) - mu * mu;
    float inv = rsqrtf(var + 1e-5f);
    float4 gg = *reinterpret_cast<const float4*>(&g[t * 4]);
    float4 bb = *reinterpret_cast<const float4*>(&bt[t * 4]);
    float4 o;
    o.x = (v.x - mu) * inv * gg.x + bb.x;
    o.y = (v.y - mu) * inv * gg.y + bb.y;
    o.z = (v.z - mu) * inv * gg.z + bb.z;
    o.w = (v.w - mu) * inv * gg.w + bb.w;
    *reinterpret_cast<float4*>(&out[(size_t)row * 512 + t * 4]) = o;
    if (outh) {
        *(uint32_t*)&outh[(size_t)row * 512 + t * 4]     = pack_f16(o.x, o.y);
        *(uint32_t*)&outh[(size_t)row * 512 + t * 4 + 2] = pack_f16(o.z, o.w);
    }
}

// ---------------- gate: top-1 routing ---------------------------------------
__global__ void __launch_bounds__(256) gate_k(
    const float* __restrict__ x, const float* __restrict__ gw,
    const float* __restrict__ gb)
{
    int warp = threadIdx.x >> 5, lane = threadIdx.x & 31;
    int tok = blockIdx.x * 8 + warp;
    float s0 = 0, s1 = 0, s2 = 0, s3 = 0;
    const float* xr = &x[(size_t)tok * 512];
#pragma unroll
    for (int d = lane * 4; d < 512; d += 128) {
        float4 xv = *reinterpret_cast<const float4*>(&xr[d]);
        float4 w0 = *reinterpret_cast<const float4*>(&gw[d]);
        float4 w1 = *reinterpret_cast<const float4*>(&gw[512 + d]);
        float4 w2 = *reinterpret_cast<const float4*>(&gw[1024 + d]);
        float4 w3 = *reinterpret_cast<const float4*>(&gw[1536 + d]);
        s0 += xv.x * w0.x + xv.y * w0.y + xv.z * w0.z + xv.w * w0.w;
        s1 += xv.x * w1.x + xv.y * w1.y + xv.z * w1.z + xv.w * w1.w;
        s2 += xv.x * w2.x + xv.y * w2.y + xv.z * w2.z + xv.w * w2.w;
        s3 += xv.x * w3.x + xv.y * w3.y + xv.z * w3.z + xv.w * w3.w;
    }
#pragma unroll
    for (int off = 16; off >= 1; off >>= 1) {
        s0 += __shfl_xor_sync(0xffffffffu, s0, off);
        s1 += __shfl_xor_sync(0xffffffffu, s1, off);
        s2 += __shfl_xor_sync(0xffffffffu, s2, off);
        s3 += __shfl_xor_sync(0xffffffffu, s3, off);
    }
    if (lane == 0) {
        s0 += gb[0]; s1 += gb[1]; s2 += gb[2]; s3 += gb[3];
        int best = 0; float bv = s0;
        if (s1 > bv) { bv = s1; best = 1; }
        if (s2 > bv) { bv = s2; best = 2; }
        if (s3 > bv) { bv = s3; best = 3; }
        int pos = atomicAdd(&g_cnt[best], 1);
        g_list[best * NTOK + pos] = tok;
    }
}

// ---------------- launch ----------------------------------------------------
extern "C" void kernel_launch(void* const* d_in, const int* in_sizes, int n_in,
                              void* d_out, int out_size)
{
    const float* x        = (const float*)d_in[0];
    const float* memory   = (const float*)d_in[1];
    const float* sa_in_w  = (const float*)d_in[2];
    const float* sa_in_b  = (const float*)d_in[3];
    const float* sa_out_w = (const float*)d_in[4];
    const float* sa_out_b = (const float*)d_in[5];
    const float* ca_in_w  = (const float*)d_in[6];
    const float* ca_in_b  = (const float*)d_in[7];
    const float* ca_out_w = (const float*)d_in[8];
    const float* ca_out_b = (const float*)d_in[9];
    const float* gate_w   = (const float*)d_in[10];
    const float* gate_b   = (const float*)d_in[11];
    const float* w1       = (const float*)d_in[12];
    const float* b1       = (const float*)d_in[13];
    const float* w2       = (const float*)d_in[14];
    const float* b2       = (const float*)d_in[15];
    const float* ln1_g    = (const float*)d_in[16];
    const float* ln1_b    = (const float*)d_in[17];
    const float* ln2_g    = (const float*)d_in[18];
    const float* ln2_b    = (const float*)d_in[19];
    const float* ln3_g    = (const float*)d_in[20];
    const float* ln3_b    = (const float*)d_in[21];
    float* out = (float*)d_out;

    float *tmp, *x1, *x2;
    __half *qk, *vt, *attnh, *ah, *bh, *hbuf;
    __half *wsain, *wsaout, *wcain, *wcaout, *w1th, *w2th;
    cudaGetSymbolAddress((void**)&qk,     g_qkv);
    cudaGetSymbolAddress((void**)&vt,     g_vt);
    cudaGetSymbolAddress((void**)&attnh,  g_attnh);
    cudaGetSymbolAddress((void**)&ah,     g_ah);
    cudaGetSymbolAddress((void**)&bh,     g_bh);
    cudaGetSymbolAddress((void**)&hbuf,   g_hbuf);
    cudaGetSymbolAddress((void**)&tmp,    g_tmp);
    cudaGetSymbolAddress((void**)&x1,     g_x1);
    cudaGetSymbolAddress((void**)&x2,     g_x2);
    cudaGetSymbolAddress((void**)&wsain,  g_wsain);
    cudaGetSymbolAddress((void**)&wsaout, g_wsaout);
    cudaGetSymbolAddress((void**)&wcain,  g_wcain);
    cudaGetSymbolAddress((void**)&wcaout, g_wcaout);
    cudaGetSymbolAddress((void**)&w1th,   g_w1t);
    cudaGetSymbolAddress((void**)&w2th,   g_w2t);

    cudaFuncSetAttribute(flash_attn, cudaFuncAttributeMaxDynamicSharedMemorySize,
                         FLASH_SMEM);
    cudaFuncSetAttribute(gemm_h, cudaFuncAttributeMaxDynamicSharedMemorySize,
                         GEMMH_SMEM);
    cudaFuncSetAttribute(gemm_projh, cudaFuncAttributeMaxDynamicSharedMemorySize,
                         GEMMH_SMEM);
    cudaFuncSetAttribute(gemm_moeh<true, false>,
                         cudaFuncAttributeMaxDynamicSharedMemorySize, GEMMH_SMEM);
    cudaFuncSetAttribute(gemm_moeh<false, true>,
                         cudaFuncAttributeMaxDynamicSharedMemorySize, GEMMH_SMEM);

    zero_cnt_kernel<<<1, 32>>>();
    // one-time conversions (per replay)
    cvt_h<<<4096, 256>>>(x, ah, NTOK * 512);
    cvt_h<<<4096, 256>>>(memory, bh, NTOK * 512);
    cvt_h<<<768, 256>>>(sa_in_w, wsain, 1536 * 512);
    cvt_h<<<256, 256>>>(sa_out_w, wsaout, 512 * 512);
    cvt_h<<<768, 256>>>(ca_in_w, wcain, 1536 * 512);
    cvt_h<<<256, 256>>>(ca_out_w, wcaout, 512 * 512);
    transpose_h<<<dim3(64, 16, 4), dim3(32, 8)>>>(w1, w1th, 512, 2048);
    transpose_h<<<dim3(16, 64, 4), dim3(32, 8)>>>(w2, w2th, 2048, 512);

    // --- self-attention ---
    gemm_projh<<<dim3(24, 64), 256, GEMMH_SMEM>>>(ah, wsain, sa_in_b, qk, 1024,
                                                  vt, NTOK, 1536, 512, 1024, 512);
    flash_attn<<<dim3(32, 16), 256, FLASH_SMEM>>>(qk, 1024, qk + 512, 1024, vt,
                                                  attnh, SEQ);
    gemm_h<<<dim3(8, 64), 256, GEMMH_SMEM>>>(attnh, wsaout, sa_out_b, x, tmp,
                                             NTOK, 512, 512);
    layernorm_k<<<NTOK, 128>>>(tmp, ln1_g, ln1_b, x1, ah);

    // --- cross-attention ---
    gemm_projh<<<dim3(8, 64), 256, GEMMH_SMEM>>>(ah, wcain, ca_in_b, qk, 512,
                                                 vt, NTOK, 512, 512, 512, 512);
    gemm_projh<<<dim3(16, 64), 256, GEMMH_SMEM>>>(bh, wcain + 512 * 512,
                                                  ca_in_b + 512,
                                                  qk + (size_t)NTOK * 512, 512,
                                                  vt, NTOK, 1024, 512, 512, 0);
    flash_attn<<<dim3(32, 16), 256, FLASH_SMEM>>>(qk, 512,
                                                  qk + (size_t)NTOK * 512, 512,
                                                  vt, attnh, SEQ);
    gemm_h<<<dim3(8, 64), 256, GEMMH_SMEM>>>(attnh, wcaout, ca_out_b, x1, tmp,
                                             NTOK, 512, 512);
    layernorm_k<<<NTOK, 128>>>(tmp, ln2_g, ln2_b, x2, ah);

    // --- MoE FFN (top-1 routed) ---
    gate_k<<<NTOK / 8, 256>>>(x2, gate_w, gate_b);
    gemm_moeh<true,  false><<<dim3(32, 256), 256, GEMMH_SMEM>>>(
        ah, w1th, b1, nullptr, hbuf, nullptr, 512, 2048);
    gemm_moeh<false, true ><<<dim3(8,  256), 256, GEMMH_SMEM>>>(
        hbuf, w2th, b2, x2, nullptr, tmp, 2048, 512);
    layernorm_k<<<NTOK, 128>>>(tmp, ln3_g, ln3_b, out, nullptr);
}